// round 5
// baseline (speedup 1.0000x reference)
#include <cuda_runtime.h>
#include <cstdint>

// ExplainedRNN: fused 2-layer GRU (B=2048, T=1024, D=64, H=32) + sigmoid head.
// 128 blocks x 4 warps (1 warp/SMSP). Warp = 4 batch rows; lane j owns hidden
// unit j of both layers for all 4 rows. Weights in smem as a per-lane blob of
// 480 floats (stride 484 -> conflict-free LDS.128); each weight quad feeds
// FMAs for 4 rows (4x crossbar amortization). Packed fma.rn.f32x2 throughout.
// Ping-pong x/h buffers with the T-loop unrolled by 2 so all buffer pointers
// are loop-invariant (LDS immediate offsets). Step is software-pipelined so
// both __syncwarp/LDS latency windows are covered by independent FFMA2 work.

#define B_ 2048
#define T_ 1024
#define D_ 64
#define H_ 32
#define WS 484               // per-lane weight stride (floats); 484 % 32 == 4
#define WARPS_PER_BLOCK 4
#define R_ 4                 // rows per warp

#define XPLANE (WARPS_PER_BLOCK * R_ * 64)   // one x buffer (floats)
#define HPLANE (WARPS_PER_BLOCK * R_ * 32)   // one h buffer (floats)

typedef unsigned long long ull;

__device__ __forceinline__ ull ffma2(ull a, ull b, ull c) {
    ull d;
    asm("fma.rn.f32x2 %0, %1, %2, %3;" : "=l"(d) : "l"(a), "l"(b), "l"(c));
    return d;
}
__device__ __forceinline__ ull packf(float lo) {   // (lo, 0.0f)
    return (ull)__float_as_uint(lo);
}
__device__ __forceinline__ float redf(ull v) {
    return __uint_as_float((unsigned)(v & 0xffffffffull)) +
           __uint_as_float((unsigned)(v >> 32));
}
__device__ __forceinline__ float sigmoidf_(float v) {
    return __fdividef(1.0f, 1.0f + __expf(-v));
}
__device__ __forceinline__ float tanhf_(float p) {
    float ap = fabsf(p);
    float e  = __expf(-2.0f * ap);
    float t  = __fdividef(1.0f - e, 1.0f + e);
    return copysignf(t, p);
}

struct StepCtx {
    const float* wsj;
    const float* xrow[R_];
    float bx0[3], bh0[3], bx1[3], bh1[3];
};

// One GRU timestep over both layers. Reads x[p],h0[p],h1[p]; writes h0[q],h1[q];
// stages x_{t+1} into xq and prefetches x_{t+2} into nx.
__device__ __forceinline__ void gru_step(
    const StepCtx& c, int j, int t,
    const float* xp, float* xq,
    const float* h0p, float* h0q,
    const float* h1p, float* h1q,
    float (&h0)[R_], float (&h1)[R_], float2 (&nx)[R_])
{
    const float* wsj = c.wsj;

    // ---- (1) Layer-0 input dots on x_t
    ull ax[R_][3], ah[R_][3];
    #pragma unroll
    for (int r = 0; r < R_; ++r)
        #pragma unroll
        for (int g = 0; g < 3; ++g) {
            ax[r][g] = packf(c.bx0[g]);
            ah[r][g] = packf(c.bh0[g]);
        }
    #pragma unroll
    for (int dd = 0; dd < 16; ++dd) {
        ulonglong2 v[R_];
        #pragma unroll
        for (int r = 0; r < R_; ++r)
            v[r] = *(const ulonglong2*)(xp + r * 64 + dd * 4);
        #pragma unroll
        for (int g = 0; g < 3; ++g) {
            const ulonglong2 wq = *(const ulonglong2*)(wsj + (dd * 3 + g) * 4);
            #pragma unroll
            for (int r = 0; r < R_; ++r) {
                ax[r][g] = ffma2(v[r].x, wq.x, ax[r][g]);
                ax[r][g] = ffma2(v[r].y, wq.y, ax[r][g]);
            }
        }
    }
    // ---- (2) Layer-0 hidden dots on h0[p]
    #pragma unroll
    for (int kk = 0; kk < 8; ++kk) {
        ulonglong2 v[R_];
        #pragma unroll
        for (int r = 0; r < R_; ++r)
            v[r] = *(const ulonglong2*)(h0p + r * 32 + kk * 4);
        #pragma unroll
        for (int g = 0; g < 3; ++g) {
            const ulonglong2 wq = *(const ulonglong2*)(wsj + 192 + (kk * 3 + g) * 4);
            #pragma unroll
            for (int r = 0; r < R_; ++r) {
                ah[r][g] = ffma2(v[r].x, wq.x, ah[r][g]);
                ah[r][g] = ffma2(v[r].y, wq.y, ah[r][g]);
            }
        }
    }
    // ---- (3) Layer-0 activations; store h0[q]
    #pragma unroll
    for (int r = 0; r < R_; ++r) {
        float xr = redf(ax[r][0]), xz = redf(ax[r][1]), xn = redf(ax[r][2]);
        float hr = redf(ah[r][0]), hz = redf(ah[r][1]), hn = redf(ah[r][2]);
        float rr = sigmoidf_(xr + hr), z = sigmoidf_(xz + hz);
        float n  = tanhf_(xn + rr * hn);
        float hv = n + z * (h0[r] - n);           // == (1-z)*n + z*h
        h0[r] = hv;
        h0q[r * 32 + j] = hv;
    }

    // ---- (4) Layer-1 HIDDEN dots on h1[p] — independent of the h0q store,
    //          covers the store->sync->load window with FMA work.
    ull ax1[R_][3];
    #pragma unroll
    for (int r = 0; r < R_; ++r)
        #pragma unroll
        for (int g = 0; g < 3; ++g) {
            ax1[r][g] = packf(c.bx1[g]);
            ah[r][g]  = packf(c.bh1[g]);
        }
    #pragma unroll
    for (int kk = 0; kk < 8; ++kk) {
        ulonglong2 hv[R_];
        #pragma unroll
        for (int r = 0; r < R_; ++r)
            hv[r] = *(const ulonglong2*)(h1p + r * 32 + kk * 4);
        #pragma unroll
        for (int g = 0; g < 3; ++g) {
            const ulonglong2 wh = *(const ulonglong2*)(wsj + 384 + (kk * 3 + g) * 4);
            #pragma unroll
            for (int r = 0; r < R_; ++r) {
                ah[r][g] = ffma2(hv[r].x, wh.x, ah[r][g]);
                ah[r][g] = ffma2(hv[r].y, wh.y, ah[r][g]);
            }
        }
    }
    __syncwarp();   // h0[q] visible to all lanes

    // ---- (5) Layer-1 input dots on h0[q]
    #pragma unroll
    for (int kk = 0; kk < 8; ++kk) {
        ulonglong2 iv[R_];
        #pragma unroll
        for (int r = 0; r < R_; ++r)
            iv[r] = *(const ulonglong2*)(h0q + r * 32 + kk * 4);
        #pragma unroll
        for (int g = 0; g < 3; ++g) {
            const ulonglong2 wi = *(const ulonglong2*)(wsj + 288 + (kk * 3 + g) * 4);
            #pragma unroll
            for (int r = 0; r < R_; ++r) {
                ax1[r][g] = ffma2(iv[r].x, wi.x, ax1[r][g]);
                ax1[r][g] = ffma2(iv[r].y, wi.y, ax1[r][g]);
            }
        }
    }
    // ---- (6) Layer-1 activations; store h1[q]
    #pragma unroll
    for (int r = 0; r < R_; ++r) {
        float xr = redf(ax1[r][0]), xz = redf(ax1[r][1]), xn = redf(ax1[r][2]);
        float hr = redf(ah[r][0]),  hz = redf(ah[r][1]),  hn = redf(ah[r][2]);
        float rr = sigmoidf_(xr + hr), z = sigmoidf_(xz + hz);
        float n  = tanhf_(xn + rr * hn);
        float hv = n + z * (h1[r] - n);
        h1[r] = hv;
        h1q[r * 32 + j] = hv;
    }

    // ---- (7) Stage x_{t+1}; prefetch x_{t+2}. Covers the h1q store->sync
    //          window (plus next iteration's x dots).
    #pragma unroll
    for (int r = 0; r < R_; ++r)
        ((float2*)(xq + r * 64))[j] = nx[r];
    if (t + 2 < T_) {
        #pragma unroll
        for (int r = 0; r < R_; ++r)
            nx[r] = ((const float2*)(c.xrow[r] + (t + 2) * D_))[j];
    }
    __syncwarp();   // h1[q] + x[q] visible
}

__global__ void __launch_bounds__(WARPS_PER_BLOCK * 32, 1)
gru_fused_kernel(const float* __restrict__ x,
                 const float* __restrict__ wih0, const float* __restrict__ whh0,
                 const float* __restrict__ bih0, const float* __restrict__ bhh0,
                 const float* __restrict__ wih1, const float* __restrict__ whh1,
                 const float* __restrict__ bih1, const float* __restrict__ bhh1,
                 const float* __restrict__ wcls, const float* __restrict__ bcls,
                 float* __restrict__ out)
{
    extern __shared__ float smem[];
    float* ws  = smem;                         // 32 * WS weights
    float* xb  = ws  + 32 * WS;                // [2][4 warps][R][64]
    float* h0b = xb  + 2 * XPLANE;             // [2][4][R][32]
    float* h1b = h0b + 2 * HPLANE;             // [2][4][R][32]

    const int tid = threadIdx.x;
    const int wid = tid >> 5;
    const int j   = tid & 31;

    // ---- Fill per-lane weight blob (ordered exactly as the quad loops read it)
    //   [0,192):   ih0   (dd*3+g)*4+u  -> wih0[(g*32+lj)*64 + dd*4+u]
    //   [192,288): hh0   (kk*3+g)*4+u  -> whh0[(g*32+lj)*32 + kk*4+u]
    //   [288,384): ih1   (kk*3+g)*4+u  -> wih1[(g*32+lj)*32 + kk*4+u]
    //   [384,480): hh1   (kk*3+g)*4+u  -> whh1[(g*32+lj)*32 + kk*4+u]
    for (int e = tid; e < 32 * 480; e += WARPS_PER_BLOCK * 32) {
        int lj = e / 480, idx = e - lj * 480;
        float v;
        if (idx < 192) {
            int u = idx & 3, gq = idx >> 2, g = gq % 3, dd = gq / 3;
            v = wih0[(g * H_ + lj) * D_ + dd * 4 + u];
        } else if (idx < 288) {
            int r2 = idx - 192;
            int u = r2 & 3, gq = r2 >> 2, g = gq % 3, kk = gq / 3;
            v = whh0[(g * H_ + lj) * H_ + kk * 4 + u];
        } else if (idx < 384) {
            int r2 = idx - 288;
            int u = r2 & 3, gq = r2 >> 2, g = gq % 3, kk = gq / 3;
            v = wih1[(g * H_ + lj) * H_ + kk * 4 + u];
        } else {
            int r2 = idx - 384;
            int u = r2 & 3, gq = r2 >> 2, g = gq % 3, kk = gq / 3;
            v = whh1[(g * H_ + lj) * H_ + kk * 4 + u];
        }
        ws[lj * WS + idx] = v;
    }
    __syncthreads();

    // ---- Per-warp row assignment
    const int gw = blockIdx.x * WARPS_PER_BLOCK + wid;   // 0..511
    const int r0 = gw * R_;

    float* x0  = xb  + wid * (R_ * 64);
    float* x1  = x0  + XPLANE;
    float* h00 = h0b + wid * (R_ * 32);
    float* h01 = h00 + HPLANE;
    float* h10 = h1b + wid * (R_ * 32);
    float* h11 = h10 + HPLANE;

    StepCtx c;
    c.wsj = ws + j * WS;
    #pragma unroll
    for (int g = 0; g < 3; ++g) {
        c.bx0[g] = bih0[g * H_ + j];  c.bh0[g] = bhh0[g * H_ + j];
        c.bx1[g] = bih1[g * H_ + j];  c.bh1[g] = bhh1[g * H_ + j];
    }

    // ---- Init: h=0 in buffer 0; stage x_0 into buffer 0; nx holds x_1.
    float h0[R_], h1[R_];
    float2 nx[R_];
    #pragma unroll
    for (int r = 0; r < R_; ++r) {
        h0[r] = 0.0f; h1[r] = 0.0f;
        h00[r * 32 + j] = 0.0f;
        h10[r * 32 + j] = 0.0f;
        c.xrow[r] = x + (size_t)(r0 + r) * T_ * D_;
        ((float2*)(x0 + r * 64))[j] = ((const float2*)c.xrow[r])[j];   // x_0
        nx[r] = ((const float2*)(c.xrow[r] + D_))[j];                  // x_1
    }
    __syncwarp();

    // ---- T-loop unrolled by 2: all buffer pointers are loop-invariant.
    #pragma unroll 1
    for (int t = 0; t < T_; t += 2) {
        gru_step(c, j, t,     x0, x1, h00, h01, h10, h11, h0, h1, nx);
        gru_step(c, j, t + 1, x1, x0, h01, h00, h11, h10, h0, h1, nx);
    }

    // ---- Outputs: [ y (2048) | h_last0 (2048*32) | h_last1 (2048*32) ]
    #pragma unroll
    for (int r = 0; r < R_; ++r) {
        out[B_ + (r0 + r) * H_ + j]           = h0[r];
        out[B_ + B_ * H_ + (r0 + r) * H_ + j] = h1[r];
    }

    const float wcj = wcls[j];
    float p[R_];
    #pragma unroll
    for (int r = 0; r < R_; ++r) p[r] = h1[r] * wcj;
    #pragma unroll
    for (int o = 16; o; o >>= 1) {
        #pragma unroll
        for (int r = 0; r < R_; ++r)
            p[r] += __shfl_xor_sync(0xffffffffu, p[r], o);
    }
    if (j == 0) {
        const float bc = bcls[0];
        #pragma unroll
        for (int r = 0; r < R_; ++r)
            out[r0 + r] = sigmoidf_(p[r] + bc);
    }
}

extern "C" void kernel_launch(void* const* d_in, const int* in_sizes, int n_in,
                              void* d_out, int out_size)
{
    const float* x    = (const float*)d_in[0];
    const float* wih0 = (const float*)d_in[1];
    const float* whh0 = (const float*)d_in[2];
    const float* bih0 = (const float*)d_in[3];
    const float* bhh0 = (const float*)d_in[4];
    const float* wih1 = (const float*)d_in[5];
    const float* whh1 = (const float*)d_in[6];
    const float* bih1 = (const float*)d_in[7];
    const float* bhh1 = (const float*)d_in[8];
    const float* wcls = (const float*)d_in[9];
    const float* bcls = (const float*)d_in[10];
    float* out = (float*)d_out;

    const int smem_bytes = (32 * WS + 2 * XPLANE + 4 * HPLANE) * (int)sizeof(float);
    static bool attr_set = false;
    if (!attr_set) {
        cudaFuncSetAttribute(gru_fused_kernel,
                             cudaFuncAttributeMaxDynamicSharedMemorySize, smem_bytes);
        attr_set = true;
    }

    const int total_warps = B_ / R_;                          // 512
    const int grid = total_warps / WARPS_PER_BLOCK;           // 128
    gru_fused_kernel<<<grid, WARPS_PER_BLOCK * 32, smem_bytes>>>(
        x, wih0, whh0, bih0, bhh0, wih1, whh1, bih1, bhh1, wcls, bcls, out);
}

// round 13
// speedup vs baseline: 1.4514x; 1.4514x over previous
#include <cuda_runtime.h>
#include <cstdint>

// ExplainedRNN: fused 2-layer GRU (B=2048, T=1024, D=64, H=32) + sigmoid head.
// 128 blocks x 8 warps = 4 warp-pairs/block, pair = {A: wid=p, B: wid=p+4}
// (same SMSP since smsp = wid%4 -> 2 warps/SMSP for latency hiding).
// Pair owns 4 batch rows. Warp A runs layer 0 for all t; warp B runs layer 1
// one timestep behind, consuming A's h0 stream through double-buffered smem.
// One named barrier (64 threads) per timestep. Input-side weights live in a
// per-lane smem blob (stride 484 -> conflict-free LDS.128); recurrent weights
// (w_hh0 for A, w_hh1 for B) are register-cached. r/z gate accumulators are
// merged (x-side + h-side share one register pair; bias pre-summed).
// x staging/prefetch hoisted to the head of stepA (independent work that
// covers the LDS ramp). Packed fma.rn.f32x2 throughout.

#define B_ 2048
#define T_ 1024
#define D_ 64
#define H_ 32
#define WS 484               // per-lane weight stride (floats); 484 % 32 == 4
#define PAIRS 4              // warp pairs per block
#define R_ 4                 // rows per pair

#define XPLANE (PAIRS * R_ * 64)
#define HPLANE (PAIRS * R_ * 32)

typedef unsigned long long ull;

static __device__ __forceinline__ ull ffma2(ull a, ull b, ull c) {
    ull d;
    asm("fma.rn.f32x2 %0, %1, %2, %3;" : "=l"(d) : "l"(a), "l"(b), "l"(c));
    return d;
}
static __device__ __forceinline__ ull packf(float lo) {   // (lo, 0.0f)
    return (ull)__float_as_uint(lo);
}
static __device__ __forceinline__ float redf(ull v) {
    return __uint_as_float((unsigned)(v & 0xffffffffull)) +
           __uint_as_float((unsigned)(v >> 32));
}
static __device__ __forceinline__ float sigmoidf_(float v) {
    return __fdividef(1.0f, 1.0f + __expf(-v));
}
static __device__ __forceinline__ float tanhf_(float p) {
    float ap = fabsf(p);
    float e  = __expf(-2.0f * ap);
    float t  = __fdividef(1.0f - e, 1.0f + e);
    return copysignf(t, p);
}
static __device__ __forceinline__ void barp(int id) {
    asm volatile("bar.sync %0, 64;" :: "r"(id) : "memory");
}

// ---- Warp A: one layer-0 step. Reads x[p], h0rd; writes h0wr; stages x.
//      Recurrent weights whr[kk][g][half] live in registers.
//      brz0[g] = bih0[g]+bhh0[g] for g in {r,z}; bxn/bhn split for the n gate.
__device__ __forceinline__ void stepA(
    const float* wsj, int j, int t,
    const float* xp, float* xq,
    const float* h0rd, float* h0wr,
    const ull (&whr)[8][3][2],
    const float* const (&xrow)[R_], float (&h0)[R_], float2 (&nx)[R_],
    const float (&brz0)[2], float bxn, float bhn)
{
    // ---- stage x_{t+1} into xq (read by nobody until next iteration) and
    //      prefetch x_{t+2}: independent work that covers the LDS ramp.
    #pragma unroll
    for (int r = 0; r < R_; ++r)
        ((float2*)(xq + r * 64))[j] = nx[r];
    if (t + 2 < T_) {
        #pragma unroll
        for (int r = 0; r < R_; ++r)
            nx[r] = ((const float2*)(xrow[r] + (t + 2) * D_))[j];
    }

    // accumulators: [0]=r (merged), [1]=z (merged), [2]=xn, [3]=hn
    ull acc[R_][4];
    #pragma unroll
    for (int r = 0; r < R_; ++r) {
        acc[r][0] = packf(brz0[0]);
        acc[r][1] = packf(brz0[1]);
        acc[r][2] = packf(bxn);
        acc[r][3] = packf(bhn);
    }
    // input dots: 64-long, 16 quads (weights from smem); g=0,1 -> merged, g=2 -> xn
    #pragma unroll
    for (int dd = 0; dd < 16; ++dd) {
        ulonglong2 v[R_];
        #pragma unroll
        for (int r = 0; r < R_; ++r)
            v[r] = *(const ulonglong2*)(xp + r * 64 + dd * 4);
        #pragma unroll
        for (int g = 0; g < 3; ++g) {
            const ulonglong2 wq = *(const ulonglong2*)(wsj + (dd * 3 + g) * 4);
            #pragma unroll
            for (int r = 0; r < R_; ++r) {
                acc[r][g] = ffma2(v[r].x, wq.x, acc[r][g]);
                acc[r][g] = ffma2(v[r].y, wq.y, acc[r][g]);
            }
        }
    }
    // hidden dots: 32-long, 8 quads (weights from REGISTERS); g=0,1 -> merged, g=2 -> hn
    #pragma unroll
    for (int kk = 0; kk < 8; ++kk) {
        ulonglong2 v[R_];
        #pragma unroll
        for (int r = 0; r < R_; ++r)
            v[r] = *(const ulonglong2*)(h0rd + r * 32 + kk * 4);
        #pragma unroll
        for (int g = 0; g < 3; ++g) {
            const int dst = (g == 2) ? 3 : g;
            #pragma unroll
            for (int r = 0; r < R_; ++r) {
                acc[r][dst] = ffma2(v[r].x, whr[kk][g][0], acc[r][dst]);
                acc[r][dst] = ffma2(v[r].y, whr[kk][g][1], acc[r][dst]);
            }
        }
    }
    // activations; store h0wr
    #pragma unroll
    for (int r = 0; r < R_; ++r) {
        float rr = sigmoidf_(redf(acc[r][0]));
        float z  = sigmoidf_(redf(acc[r][1]));
        float n  = tanhf_(redf(acc[r][2]) + rr * redf(acc[r][3]));
        float hv = n + z * (h0[r] - n);           // == (1-z)*n + z*h
        h0[r] = hv;
        h0wr[r * 32 + j] = hv;
    }
}

// ---- Warp B: one layer-1 step. Reads h0rd (A's output), h1rd; writes h1wr.
//      w_ih1 from smem; w_hh1 register-cached.
__device__ __forceinline__ void stepB(
    const float* wsj, int j,
    const float* h0rd, const float* h1rd, float* h1wr,
    const ull (&whr)[8][3][2],
    float (&h1)[R_],
    const float (&brz1)[2], float bxn, float bhn)
{
    ull acc[R_][4];
    #pragma unroll
    for (int r = 0; r < R_; ++r) {
        acc[r][0] = packf(brz1[0]);
        acc[r][1] = packf(brz1[1]);
        acc[r][2] = packf(bxn);
        acc[r][3] = packf(bhn);
    }
    #pragma unroll
    for (int kk = 0; kk < 8; ++kk) {
        ulonglong2 iv[R_], hv[R_];
        #pragma unroll
        for (int r = 0; r < R_; ++r) {
            iv[r] = *(const ulonglong2*)(h0rd + r * 32 + kk * 4);
            hv[r] = *(const ulonglong2*)(h1rd + r * 32 + kk * 4);
        }
        #pragma unroll
        for (int g = 0; g < 3; ++g) {
            const ulonglong2 wi = *(const ulonglong2*)(wsj + 288 + (kk * 3 + g) * 4);
            const int dst = (g == 2) ? 3 : g;
            #pragma unroll
            for (int r = 0; r < R_; ++r) {
                acc[r][g]   = ffma2(iv[r].x, wi.x, acc[r][g]);
                acc[r][g]   = ffma2(iv[r].y, wi.y, acc[r][g]);
                acc[r][dst] = ffma2(hv[r].x, whr[kk][g][0], acc[r][dst]);
                acc[r][dst] = ffma2(hv[r].y, whr[kk][g][1], acc[r][dst]);
            }
        }
    }
    #pragma unroll
    for (int r = 0; r < R_; ++r) {
        float rr = sigmoidf_(redf(acc[r][0]));
        float z  = sigmoidf_(redf(acc[r][1]));
        float n  = tanhf_(redf(acc[r][2]) + rr * redf(acc[r][3]));
        float hv = n + z * (h1[r] - n);
        h1[r] = hv;
        h1wr[r * 32 + j] = hv;
    }
}

__global__ void __launch_bounds__(256, 1)
gru_fused_kernel(const float* __restrict__ x,
                 const float* __restrict__ wih0, const float* __restrict__ whh0,
                 const float* __restrict__ bih0, const float* __restrict__ bhh0,
                 const float* __restrict__ wih1, const float* __restrict__ whh1,
                 const float* __restrict__ bih1, const float* __restrict__ bhh1,
                 const float* __restrict__ wcls, const float* __restrict__ bcls,
                 float* __restrict__ out)
{
    extern __shared__ float smem[];
    float* ws  = smem;                         // 32 * WS weights
    float* xb  = ws  + 32 * WS;                // [2][PAIRS][R][64]
    float* h0b = xb  + 2 * XPLANE;             // [2][PAIRS][R][32]
    float* h1b = h0b + 2 * HPLANE;             // [2][PAIRS][R][32]

    const int tid = threadIdx.x;
    const int wid = tid >> 5;
    const int j   = tid & 31;

    // ---- Fill per-lane weight blob (ordered exactly as the quad loops read it)
    //   [0,192):   ih0   (dd*3+g)*4+u  -> wih0[(g*32+lj)*64 + dd*4+u]
    //   [192,288): hh0   (kk*3+g)*4+u  -> whh0[(g*32+lj)*32 + kk*4+u]
    //   [288,384): ih1   (kk*3+g)*4+u  -> wih1[(g*32+lj)*32 + kk*4+u]
    //   [384,480): hh1   (kk*3+g)*4+u  -> whh1[(g*32+lj)*32 + kk*4+u]
    for (int e = tid; e < 32 * 480; e += 256) {
        int lj = e / 480, idx = e - lj * 480;
        float v;
        if (idx < 192) {
            int u = idx & 3, gq = idx >> 2, g = gq % 3, dd = gq / 3;
            v = wih0[(g * H_ + lj) * D_ + dd * 4 + u];
        } else if (idx < 288) {
            int r2 = idx - 192;
            int u = r2 & 3, gq = r2 >> 2, g = gq % 3, kk = gq / 3;
            v = whh0[(g * H_ + lj) * H_ + kk * 4 + u];
        } else if (idx < 384) {
            int r2 = idx - 288;
            int u = r2 & 3, gq = r2 >> 2, g = gq % 3, kk = gq / 3;
            v = wih1[(g * H_ + lj) * H_ + kk * 4 + u];
        } else {
            int r2 = idx - 384;
            int u = r2 & 3, gq = r2 >> 2, g = gq % 3, kk = gq / 3;
            v = whh1[(g * H_ + lj) * H_ + kk * 4 + u];
        }
        ws[lj * WS + idx] = v;
    }

    const int pair = wid & 3;
    const bool isA = wid < 4;
    const int bar_id = pair + 1;
    const int r0 = blockIdx.x * (PAIRS * R_) + pair * R_;

    float* x0  = xb  + pair * (R_ * 64);
    float* x1  = x0  + XPLANE;
    float* h00 = h0b + pair * (R_ * 32);
    float* h01 = h00 + HPLANE;
    float* h10 = h1b + pair * (R_ * 32);
    float* h11 = h10 + HPLANE;

    const float* wsj = ws + j * WS;

    if (isA) {
        // =========================== Warp A: layer 0 ======================
        float brz0[2], bxn, bhn;
        brz0[0] = bih0[j]        + bhh0[j];
        brz0[1] = bih0[H_ + j]   + bhh0[H_ + j];
        bxn     = bih0[2 * H_ + j];
        bhn     = bhh0[2 * H_ + j];

        float h0[R_];
        const float* xrow[R_];
        float2 nx[R_];
        #pragma unroll
        for (int r = 0; r < R_; ++r) {
            h0[r] = 0.0f;
            h01[r * 32 + j] = 0.0f;                                 // h0[-1] in buf1
            xrow[r] = x + (size_t)(r0 + r) * T_ * D_;
            ((float2*)(x0 + r * 64))[j] = ((const float2*)xrow[r])[j];  // x_0
            nx[r] = ((const float2*)(xrow[r] + D_))[j];                 // x_1
        }
        __syncthreads();

        // Register-cache w_hh0 (lane j's 96 floats) from the smem blob.
        ull whr[8][3][2];
        #pragma unroll
        for (int kk = 0; kk < 8; ++kk)
            #pragma unroll
            for (int g = 0; g < 3; ++g) {
                const ulonglong2 wq = *(const ulonglong2*)(wsj + 192 + (kk * 3 + g) * 4);
                whr[kk][g][0] = wq.x;
                whr[kk][g][1] = wq.y;
            }

        // A step s: xp=buf[s&1], rd h0 buf[(s-1)&1], wr buf[s&1]; 512 even/odd pairs.
        #pragma unroll 1
        for (int t = 0; t < T_; t += 2) {
            stepA(wsj, j, t,     x0, x1, h01, h00, whr, xrow, h0, nx, brz0, bxn, bhn);
            barp(bar_id);
            stepA(wsj, j, t + 1, x1, x0, h00, h01, whr, xrow, h0, nx, brz0, bxn, bhn);
            barp(bar_id);
        }

        // h_last0
        #pragma unroll
        for (int r = 0; r < R_; ++r)
            out[B_ + (r0 + r) * H_ + j] = h0[r];
    } else {
        // =========================== Warp B: layer 1 ======================
        float brz1[2], bxn, bhn;
        brz1[0] = bih1[j]        + bhh1[j];
        brz1[1] = bih1[H_ + j]   + bhh1[H_ + j];
        bxn     = bih1[2 * H_ + j];
        bhn     = bhh1[2 * H_ + j];

        float h1[R_];
        #pragma unroll
        for (int r = 0; r < R_; ++r) {
            h1[r] = 0.0f;
            h11[r * 32 + j] = 0.0f;                                 // h1[-1] in buf1
        }
        __syncthreads();

        // Register-cache w_hh1 (lane j's 96 floats) from the smem blob.
        ull whr[8][3][2];
        #pragma unroll
        for (int kk = 0; kk < 8; ++kk)
            #pragma unroll
            for (int g = 0; g < 3; ++g) {
                const ulonglong2 wq = *(const ulonglong2*)(wsj + 384 + (kk * 3 + g) * 4);
                whr[kk][g][0] = wq.x;
                whr[kk][g][1] = wq.y;
            }

        barp(bar_id);                                         // s=0: A computes h0[0]
        stepB(wsj, j, h00, h11, h10, whr, h1, brz1, bxn, bhn); // s=1: h1[0] <- h0[0], h1[-1]
        barp(bar_id);
        #pragma unroll 1
        for (int k = 0; k < (T_ - 2) / 2; ++k) {              // s = 2..1023
            stepB(wsj, j, h01, h10, h11, whr, h1, brz1, bxn, bhn); // even s
            barp(bar_id);
            stepB(wsj, j, h00, h11, h10, whr, h1, brz1, bxn, bhn); // odd s
            barp(bar_id);
        }
        stepB(wsj, j, h01, h10, h11, whr, h1, brz1, bxn, bhn); // s=1024: h1[1023]

        // h_last1 + classifier y
        #pragma unroll
        for (int r = 0; r < R_; ++r)
            out[B_ + B_ * H_ + (r0 + r) * H_ + j] = h1[r];

        const float wcj = wcls[j];
        float p[R_];
        #pragma unroll
        for (int r = 0; r < R_; ++r) p[r] = h1[r] * wcj;
        #pragma unroll
        for (int o = 16; o; o >>= 1) {
            #pragma unroll
            for (int r = 0; r < R_; ++r)
                p[r] += __shfl_xor_sync(0xffffffffu, p[r], o);
        }
        if (j == 0) {
            const float bc = bcls[0];
            #pragma unroll
            for (int r = 0; r < R_; ++r)
                out[r0 + r] = sigmoidf_(p[r] + bc);
        }
    }
}

extern "C" void kernel_launch(void* const* d_in, const int* in_sizes, int n_in,
                              void* d_out, int out_size)
{
    const float* x    = (const float*)d_in[0];
    const float* wih0 = (const float*)d_in[1];
    const float* whh0 = (const float*)d_in[2];
    const float* bih0 = (const float*)d_in[3];
    const float* bhh0 = (const float*)d_in[4];
    const float* wih1 = (const float*)d_in[5];
    const float* whh1 = (const float*)d_in[6];
    const float* bih1 = (const float*)d_in[7];
    const float* bhh1 = (const float*)d_in[8];
    const float* wcls = (const float*)d_in[9];
    const float* bcls = (const float*)d_in[10];
    float* out = (float*)d_out;

    const int smem_bytes = (32 * WS + 2 * XPLANE + 4 * HPLANE) * (int)sizeof(float);
    static bool attr_set = false;
    if (!attr_set) {
        cudaFuncSetAttribute(gru_fused_kernel,
                             cudaFuncAttributeMaxDynamicSharedMemorySize, smem_bytes);
        attr_set = true;
    }

    const int grid = B_ / (PAIRS * R_);   // 128 blocks, 16 rows each
    gru_fused_kernel<<<grid, 256, smem_bytes>>>(
        x, wih0, whh0, bih0, bhh0, wih1, whh1, bih1, bhh1, wcls, bcls, out);
}